// round 17
// baseline (speedup 1.0000x reference)
#include <cuda_runtime.h>
#include <math.h>

constexpr int C  = 128;
constexpr int S  = 24;
constexpr int NV = S * S * S;      // 13824
constexpr int KW = 3;
constexpr int NW = KW * KW * KW;   // 27

__device__ float g_q[NV * C];
__device__ float g_k[NV * C];
__device__ float g_v[NV * C];
__device__ float g_bias[NW];
__device__ float g_wt[3 * C * C];  // transposed weights: [mat][c][o]

typedef unsigned long long u64;

// ---- packed f32x2 helpers (Blackwell FFMA2 path, PTX-only) -----------------
__device__ __forceinline__ u64 pk2(float lo, float hi) {
    u64 d;
    asm("mov.b64 %0, {%1, %2};" : "=l"(d) : "f"(lo), "f"(hi));
    return d;
}
__device__ __forceinline__ void fma2(u64& c, u64 a, u64 b) {
    asm("fma.rn.f32x2 %0, %1, %2, %0;" : "+l"(c) : "l"(a), "l"(b));
}
__device__ __forceinline__ float2 up2(u64 d) {
    float2 r;
    asm("mov.b64 {%0, %1}, %2;" : "=f"(r.x), "=f"(r.y) : "l"(d));
    return r;
}

// ---- cp.async helpers ------------------------------------------------------
__device__ __forceinline__ void cpa16(void* s, const void* g) {
    unsigned sa = (unsigned)__cvta_generic_to_shared(s);
    asm volatile("cp.async.cg.shared.global [%0], [%1], 16;" :: "r"(sa), "l"(g) : "memory");
}
__device__ __forceinline__ void cpcommit() {
    asm volatile("cp.async.commit_group;" ::: "memory");
}
__device__ __forceinline__ void cpwait0() {
    asm volatile("cp.async.wait_group 0;" ::: "memory");
}

// ---------------------------------------------------------------------------
// Prep: bias table. 288 threads, one warp per partial sum.
// ---------------------------------------------------------------------------
__global__ void prep_kernel(const float* __restrict__ rh,
                            const float* __restrict__ rw,
                            const float* __restrict__ rd) {
    __shared__ float a[9];
    int w = threadIdx.x >> 5, lane = threadIdx.x & 31;
    if (w < 9) {
        const float* p = (w < 3) ? rh : (w < 6 ? rw : rd);
        int k = w % 3;
        float s = 0.f;
        for (int c = lane; c < 64; c += 32) s += p[c * 3 + k];
#pragma unroll
        for (int o = 16; o; o >>= 1) s += __shfl_xor_sync(0xffffffffu, s, o);
        if (lane == 0) a[w] = s;
    }
    __syncthreads();
    int t = threadIdx.x;
    if (t < NW)
        g_bias[t] = a[t / 9] + a[3 + (t / 3) % 3] + a[6 + t % 3];
}

// ---------------------------------------------------------------------------
// Weight transpose: g_wt[mat][c][o] = w[mat][o][c].  grid (4,4,3), block (32,8)
// ---------------------------------------------------------------------------
__global__ void wt_kernel(const float* __restrict__ w0,
                          const float* __restrict__ w1,
                          const float* __restrict__ w2) {
    __shared__ float t[32][33];
    int mat = blockIdx.z;
    const float* w = (mat == 0) ? w0 : (mat == 1 ? w1 : w2);
    int o0 = blockIdx.y * 32, c0 = blockIdx.x * 32;
    int tx = threadIdx.x;
    for (int i = threadIdx.y; i < 32; i += 8)
        t[i][tx] = w[(o0 + i) * C + c0 + tx];
    __syncthreads();
    float* dst = g_wt + mat * C * C;
    for (int i = threadIdx.y; i < 32; i += 8)
        dst[(c0 + i) * C + o0 + tx] = t[tx][i];
}

// ---------------------------------------------------------------------------
// Fused GEMM: computes q, k, v for a 32-voxel tile in one block.
// x tile (32 vox x 128 c, 16 KB) staged once and reused by all 3 matrices;
// weights stream via 2x8KB cp.async double buffer continuously across mats.
// 128 threads; thread tile 4 voxels x 8 channels as 4 ch-pair x 4 vox FFMA2.
// ---------------------------------------------------------------------------
__global__ void __launch_bounds__(128)
gemm_kernel(const float* __restrict__ x,
            const float* __restrict__ b0,
            const float* __restrict__ b1,
            const float* __restrict__ b2) {
    extern __shared__ __align__(16) float sm[];
    float* xs = sm;                // [128][32]
    float* ws = sm + 128 * 32;     // [2][16][128]

    int tid = threadIdx.x;
    int v0 = blockIdx.x * 32;

    // stage full x tile: 1024 float4
#pragma unroll
    for (int t = 0; t < 8; t++) {
        int idx = tid + t * 128;
        int c = idx >> 3, q = idx & 7;
        cpa16(xs + c * 32 + q * 4, x + c * NV + v0 + q * 4);
    }
    cpcommit();
    // prologue: ws chunk 0 of mat 0 into buf 0
#pragma unroll
    for (int t = 0; t < 4; t++) {
        int idx = tid + t * 128;
        int r = idx >> 5, q = idx & 31;
        cpa16(ws + r * 128 + q * 4, g_wt + r * C + q * 4);
    }
    cpcommit();

    int tx = tid & 15, ty = tid >> 4;
    int ob = tx * 8;     // output-channel base
    int vb = ty * 4;     // voxel base

    for (int mat = 0; mat < 3; mat++) {
        u64 acc[4][4];   // [ch-pair][vox]
#pragma unroll
        for (int jp = 0; jp < 4; jp++)
#pragma unroll
            for (int i = 0; i < 4; i++) acc[jp][i] = 0ull;

        for (int ch = 0; ch < 8; ch++) {
            int it = mat * 8 + ch;
            cpwait0();
            __syncthreads();
            if (it < 23) {
                int nit = it + 1;
                int nm = nit >> 3, nc = nit & 7;
                const float* wsrc = g_wt + nm * C * C + nc * 16 * C;
                float* wdst = ws + (nit & 1) * 2048;
#pragma unroll
                for (int t = 0; t < 4; t++) {
                    int idx = tid + t * 128;
                    int r = idx >> 5, q = idx & 31;
                    cpa16(wdst + r * 128 + q * 4, wsrc + r * C + q * 4);
                }
                cpcommit();
            }
            const float* wb_ = ws + (it & 1) * 2048;

#pragma unroll
            for (int k = 0; k < 16; k++) {
                int c = ch * 16 + k;
                float4 xv = *(const float4*)(xs + c * 32 + vb);
                ulonglong2 wp0 = *(const ulonglong2*)(wb_ + k * 128 + ob);
                ulonglong2 wp1 = *(const ulonglong2*)(wb_ + k * 128 + ob + 4);
                u64 wq[4] = {wp0.x, wp0.y, wp1.x, wp1.y};
                u64 xb[4];
                xb[0] = pk2(xv.x, xv.x);
                xb[1] = pk2(xv.y, xv.y);
                xb[2] = pk2(xv.z, xv.z);
                xb[3] = pk2(xv.w, xv.w);
#pragma unroll
                for (int jp = 0; jp < 4; jp++)
#pragma unroll
                    for (int i = 0; i < 4; i++)
                        fma2(acc[jp][i], xb[i], wq[jp]);
            }
        }

        // epilogue for this mat
        const float* bias = (mat == 0) ? b0 : (mat == 1 ? b1 : b2);
        float* out = (mat == 0) ? g_q : (mat == 1 ? g_k : g_v);
        float4 bb0 = *(const float4*)(bias + ob);
        float4 bb1 = *(const float4*)(bias + ob + 4);
#pragma unroll
        for (int i = 0; i < 4; i++) {
            float2 a0 = up2(acc[0][i]);
            float2 a1 = up2(acc[1][i]);
            float2 a2 = up2(acc[2][i]);
            float2 a3 = up2(acc[3][i]);
            float* row = out + (size_t)(v0 + vb + i) * C + ob;
            float4 s0, s1;
            s0.x = a0.x + bb0.x; s0.y = a0.y + bb0.y;
            s0.z = a1.x + bb0.z; s0.w = a1.y + bb0.w;
            s1.x = a2.x + bb1.x; s1.y = a2.y + bb1.y;
            s1.z = a3.x + bb1.z; s1.w = a3.y + bb1.w;
            *(float4*)row       = s0;
            *(float4*)(row + 4) = s1;
        }
    }
}

// ---------------------------------------------------------------------------
// Attention: 8 warps/block = 2x2x2 voxel cube; the 4x4x4 unique K/V
// neighborhood is cp.async-staged into smem with OOB rows pre-filled from
// bk/bv (no boundary logic in the hot loops). Warp-per-voxel softmax.
// ---------------------------------------------------------------------------
__global__ void __launch_bounds__(256)
attn_kernel(const float* __restrict__ bk,
            const float* __restrict__ bv,
            float* __restrict__ out) {
    extern __shared__ __align__(16) float sm[];  // [128][128]: K rows 0-63, V rows 64-127
    const unsigned FULL = 0xffffffffu;
    int tid  = threadIdx.x;
    int lane = tid & 31;
    int wrp  = tid >> 5;

    int t = blockIdx.x;                 // 0 .. 12^3-1
    int tH = t / 144;
    int rr = t - tH * 144;
    int tW = rr / 12;
    int tD = rr - tW * 12;
    int h0 = tH * 2, w0 = tW * 2, d0 = tD * 2;

    // stage 64 K rows + 64 V rows (4x4x4 cube, OOB -> bias rows)
#pragma unroll
    for (int j = 0; j < 8; j++) {
        int r = wrp + j * 8;            // 0..63
        int a = r >> 4, b = (r >> 2) & 3, c = r & 3;
        int gh = h0 - 1 + a, gw = w0 - 1 + b, gd = d0 - 1 + c;
        bool ok = (unsigned)gh < (unsigned)S && (unsigned)gw < (unsigned)S &&
                  (unsigned)gd < (unsigned)S;
        size_t off = (size_t)((gh * S + gw) * S + gd) * C + lane * 4;
        cpa16(sm + r * 128 + lane * 4,        ok ? g_k + off : bk + lane * 4);
        cpa16(sm + (64 + r) * 128 + lane * 4, ok ? g_v + off : bv + lane * 4);
    }
    cpcommit();

    int li = (wrp >> 2) & 1, lj = (wrp >> 1) & 1, ll = wrp & 1;
    int h = h0 + li, w = w0 + lj, d = d0 + ll;
    int v = (h * S + w) * S + d;
    int base = li * 16 + lj * 4 + ll;

    const float4 qv = *(const float4*)(g_q + (size_t)v * C + lane * 4);

    // qsum over all 128 channels
    float qs = qv.x + qv.y + qv.z + qv.w;
#pragma unroll
    for (int o = 16; o; o >>= 1) qs += __shfl_xor_sync(FULL, qs, o);

    float bias = (lane < NW) ? g_bias[lane] : 0.f;

    cpwait0();
    __syncthreads();

    // QK: 27 dots from smem; lane s keeps logit_s
    float logit = 0.f;
#pragma unroll
    for (int s = 0; s < NW; s++) {
        int rid = base + (s / 9) * 16 + ((s / 3) % 3) * 4 + (s % 3);
        float4 kv = *(const float4*)(sm + rid * 128 + lane * 4);
        float p = qv.x * kv.x;
        p = fmaf(qv.y, kv.y, p);
        p = fmaf(qv.z, kv.z, p);
        p = fmaf(qv.w, kv.w, p);
#pragma unroll
        for (int o = 16; o; o >>= 1) p += __shfl_xor_sync(FULL, p, o);
        if (lane == s) logit = p;
    }

    // softmax over 27, in-warp
    float liv = (lane < NW) ? fmaf(qs, bias, logit) : -INFINITY;
    float mx = liv;
#pragma unroll
    for (int o = 16; o; o >>= 1) mx = fmaxf(mx, __shfl_xor_sync(FULL, mx, o));
    float p = (lane < NW) ? __expf(liv - mx) : 0.f;
    float ssum = p;
#pragma unroll
    for (int o = 16; o; o >>= 1) ssum += __shfl_xor_sync(FULL, ssum, o);
    float prob = p / ssum;

    // AV: weighted sum of 27 V rows from smem
    float4 acc = make_float4(0.f, 0.f, 0.f, 0.f);
#pragma unroll
    for (int s = 0; s < NW; s++) {
        int rid = base + (s / 9) * 16 + ((s / 3) % 3) * 4 + (s % 3);
        float ps = __shfl_sync(FULL, prob, s);
        float4 vv = *(const float4*)(sm + (64 + rid) * 128 + lane * 4);
        acc.x = fmaf(ps, vv.x, acc.x);
        acc.y = fmaf(ps, vv.y, acc.y);
        acc.z = fmaf(ps, vv.z, acc.z);
        acc.w = fmaf(ps, vv.w, acc.w);
    }
    *(float4*)(out + (size_t)v * C + lane * 4) = acc;
}

// ---------------------------------------------------------------------------
// Launch.  Inputs: x, wq, bq, wk, bk, wv, bv, rel_h, rel_w, rel_d
// ---------------------------------------------------------------------------
extern "C" void kernel_launch(void* const* d_in, const int* in_sizes, int n_in,
                              void* d_out, int out_size) {
    const float* x   = (const float*)d_in[0];
    const float* wq  = (const float*)d_in[1];
    const float* bq  = (const float*)d_in[2];
    const float* wk  = (const float*)d_in[3];
    const float* bk  = (const float*)d_in[4];
    const float* wv  = (const float*)d_in[5];
    const float* bv  = (const float*)d_in[6];
    const float* rh  = (const float*)d_in[7];
    const float* rw  = (const float*)d_in[8];
    const float* rd  = (const float*)d_in[9];
    float* out = (float*)d_out;

    prep_kernel<<<1, 288>>>(rh, rw, rd);

    dim3 tgrid(4, 4, 3);
    wt_kernel<<<tgrid, dim3(32, 8)>>>(wq, wk, wv);

    int gsmem = (128 * 32 + 2 * 16 * 128) * (int)sizeof(float);   // 32 KB
    cudaFuncSetAttribute(gemm_kernel, cudaFuncAttributeMaxDynamicSharedMemorySize, gsmem);
    gemm_kernel<<<NV / 32, 128, gsmem>>>(x, bq, bk, bv);

    int asmem = 128 * 128 * (int)sizeof(float);                   // 64 KB
    cudaFuncSetAttribute(attn_kernel, cudaFuncAttributeMaxDynamicSharedMemorySize, asmem);
    attn_kernel<<<(S / 2) * (S / 2) * (S / 2), 256, asmem>>>(bk, bv, out);
}